// round 4
// baseline (speedup 1.0000x reference)
#include <cuda_runtime.h>
#include <math.h>
#include <stdint.h>

// ---------------- problem constants ----------------
constexpr int B  = 2;
constexpr int C  = 32;
constexpr int NS = 32;
constexpr int NZ = 96;
constexpr int NX = 96;
constexpr int P  = NS * NZ * NX;      // 294912 per (b,c)
constexpr int NPT = B * P;            // 589824 spatial points
constexpr int M1 = 8, M2 = 12, M3 = 12;
constexpr int KS = 16, KZ = 24, KX = 12;   // kept modes per axis
constexpr float SLOPE = 0.1f;
constexpr float INV2DX = 50.0f;            // 0.5/0.01

// ---------------- scratch (device globals; no allocation) ----------------
__device__ float  g_hA[B * C * P];
__device__ float  g_hB[B * C * P];
__device__ float  g_h1[B * C * P];
__device__ float2 g_S1[B * C * NS * NZ * KX];   // 2,359,296
__device__ float2 g_S2[B * C * NS * KZ * KX];   //   589,824
__device__ float2 g_S3[B * C * KS * KZ * KX];   //   294,912
__device__ float2 g_G [B * C * KS * KZ * KX];
__device__ float2 g_T1[B * C * NS * KZ * KX];
__device__ float2 g_T2[B * C * NS * NZ * KX];
__device__ float  g_t0dx[NPT];
__device__ float  g_t0dz[NPT];
__device__ double g_sum[C];
__device__ double g_sq[C];
__device__ float  g_scale[C];
__device__ float  g_shift[C];

// twiddles (normalization folded into forward tables)
__device__ float2 g_twFx[KX * NX];
__device__ float2 g_twFz[KZ * NZ];
__device__ float2 g_twFs[KS * NS];
__device__ float2 g_twIs[NS * KS];
__device__ float2 g_twIz[NZ * KZ];
__device__ float2 g_twIx[NX * KX];

__device__ __forceinline__ float lrelu(float v) { return v > 0.f ? v : SLOPE * v; }
__device__ __forceinline__ float* hbuf(int s) { return s ? g_hB : g_hA; }

// ---------------- twiddle init ----------------
__global__ void k_init_tw() {
    int t = blockIdx.x * blockDim.x + threadIdx.x;
    int stride = gridDim.x * blockDim.x;
    for (int i = t; i < KX * NX; i += stride) {
        int k = i / NX, x = i % NX;
        double f = 2.0 * double((k * x) % NX) / NX;
        double s, c; sincospi(f, &s, &c);
        g_twFx[i] = make_float2((float)(c / NX), (float)(-s / NX));
        // inverse x: layout [x][k]
        g_twIx[x * KX + k] = make_float2((float)c, (float)s);
    }
    for (int i = t; i < KZ * NZ; i += stride) {
        int ki = i / NZ, z = i % NZ;
        int kz = (ki < M2) ? ki : ki + (NZ - KZ);   // ki-12 -> kz 84..95
        double f = 2.0 * double((kz * z) % NZ) / NZ;
        double s, c; sincospi(f, &s, &c);
        g_twFz[i] = make_float2((float)(c / NZ), (float)(-s / NZ));
        g_twIz[z * KZ + ki] = make_float2((float)c, (float)s);
    }
    for (int i = t; i < KS * NS; i += stride) {
        int ki = i / NS, s0 = i % NS;
        int ks = (ki < M1) ? ki : ki + (NS - KS);   // ki-8 -> ks 24..31
        double f = 2.0 * double((ks * s0) % NS) / NS;
        double s, c; sincospi(f, &s, &c);
        g_twFs[i] = make_float2((float)(c / NS), (float)(-s / NS));
        g_twIs[s0 * KS + ki] = make_float2((float)c, (float)s);
    }
}

// ---------------- fc0 + T0 derivatives ----------------
__global__ void k_fc0t0(const float* __restrict__ x, const float* __restrict__ w,
                        const float* __restrict__ bb) {
    int p = blockIdx.x * blockDim.x + threadIdx.x;
    if (p >= NPT) return;
    int b = p / P, p0 = p % P;
    int xx = p0 % NX;
    int z  = (p0 / NX) % NZ;
    float a0 = x[2 * p], a1 = x[2 * p + 1];
#pragma unroll
    for (int c = 0; c < C; c++)
        g_hA[(b * C + c) * P + p0] = a0 * w[c] + a1 * w[C + c] + bb[c];
    float xm = (xx > 0)      ? x[2 * (p - 1) + 1]  : 0.f;
    float xp = (xx < NX - 1) ? x[2 * (p + 1) + 1]  : 0.f;
    g_t0dx[p] = (xp - xm) * INV2DX;
    float zm = (z > 0)       ? x[2 * (p - NX) + 1] : 0.f;
    float zp = (z < NZ - 1)  ? x[2 * (p + NX) + 1] : 0.f;
    g_t0dz[p] = (zp - zm) * INV2DX;
}

// ---------------- forward DFT stages ----------------
__global__ void k_f1(int sel) {           // x axis: real 96 -> 12 modes
    int g = blockIdx.x * blockDim.x + threadIdx.x;   // line*12 + kx
    int line = g / KX, k = g % KX;
    const float* src = hbuf(sel) + line * NX;
    const float2* tw = g_twFx + k * NX;
    float re = 0.f, im = 0.f;
#pragma unroll 8
    for (int x = 0; x < NX; x++) {
        float v = src[x]; float2 t = tw[x];
        re += v * t.x; im += v * t.y;
    }
    g_S1[g] = make_float2(re, im);
}

__global__ void k_f2() {                  // z axis: 96 -> 24 modes
    int g = blockIdx.x * blockDim.x + threadIdx.x;
    int kx = g % KX, kzi = (g / KX) % KZ, bcs = g / (KX * KZ);
    const float2* src = g_S1 + bcs * (NZ * KX) + kx;
    const float2* tw  = g_twFz + kzi * NZ;
    float re = 0.f, im = 0.f;
#pragma unroll 8
    for (int z = 0; z < NZ; z++) {
        float2 v = src[z * KX]; float2 t = tw[z];
        re += v.x * t.x - v.y * t.y;
        im += v.x * t.y + v.y * t.x;
    }
    g_S2[g] = make_float2(re, im);
}

__global__ void k_f3() {                  // s axis: 32 -> 16 modes
    int g = blockIdx.x * blockDim.x + threadIdx.x;
    int kx = g % KX, kzi = (g / KX) % KZ, ksi = (g / 288) % KS, bc = g / 4608;
    const float2* src = g_S2 + bc * NS * 288 + kzi * KX + kx;
    const float2* tw  = g_twFs + ksi * NS;
    float re = 0.f, im = 0.f;
#pragma unroll 8
    for (int s = 0; s < NS; s++) {
        float2 v = src[s * 288]; float2 t = tw[s];
        re += v.x * t.x - v.y * t.y;
        im += v.x * t.y + v.y * t.x;
    }
    g_S3[(bc * KS + ksi) * 288 + kzi * KX + kx] = make_float2(re, im);
}

// ---------------- spectral multiply ----------------
__global__ void k_mul(int L, const float* __restrict__ spec) {
    int g = blockIdx.x * blockDim.x + threadIdx.x;
    int kx = g % KX, kzi = (g / KX) % KZ, ksi = (g / 288) % KS;
    int co = (g / 4608) % C, b = g / (4608 * C);
    int corner = (ksi >= M1 ? 1 : 0) + (kzi >= M2 ? 2 : 0);
    int k1 = (ksi >= M1) ? ksi - M1 : ksi;
    int k2 = (kzi >= M2) ? kzi - M2 : kzi;
    // weight element ((((L*4+corner)*C + ci)*C + co)*M1+k1)*M2+k2)*M3+kx, *2
    int wbase = ((((L * 4 + corner) * C) * C + co) * M1 + k1) * M2 + k2;
    wbase = wbase * M3 + kx;
    const int wstride = C * M1 * M2 * M3;   // per ci step (in complex elems)
    const float2* xin = g_S3 + (b * C) * 4608 + ksi * 288 + kzi * KX + kx;
    float re = 0.f, im = 0.f;
#pragma unroll 8
    for (int ci = 0; ci < C; ci++) {
        float2 a = xin[ci * 4608];
        float wr = spec[2 * (wbase + ci * wstride)];
        float wi = spec[2 * (wbase + ci * wstride) + 1];
        re += a.x * wr - a.y * wi;
        im += a.x * wi + a.y * wr;
    }
    g_G[g] = make_float2(re, im);
}

// ---------------- inverse DFT stages ----------------
__global__ void k_i1() {                  // 16 -> 32 along s
    int g = blockIdx.x * blockDim.x + threadIdx.x;
    int kx = g % KX, kzi = (g / KX) % KZ, s = (g / 288) % NS, bc = g / (288 * NS);
    const float2* src = g_G + bc * 4608 + kzi * KX + kx;
    const float2* tw  = g_twIs + s * KS;
    float re = 0.f, im = 0.f;
#pragma unroll
    for (int k = 0; k < KS; k++) {
        float2 v = src[k * 288]; float2 t = tw[k];
        re += v.x * t.x - v.y * t.y;
        im += v.x * t.y + v.y * t.x;
    }
    g_T1[g] = make_float2(re, im);
}

__global__ void k_i2() {                  // 24 -> 96 along z
    int g = blockIdx.x * blockDim.x + threadIdx.x;
    int kx = g % KX, z = (g / KX) % NZ, s = (g / (KX * NZ)) % NS, bc = g / (KX * NZ * NS);
    const float2* src = g_T1 + (bc * NS + s) * 288 + kx;
    const float2* tw  = g_twIz + z * KZ;
    float re = 0.f, im = 0.f;
#pragma unroll
    for (int k = 0; k < KZ; k++) {
        float2 v = src[k * KX]; float2 t = tw[k];
        re += v.x * t.x - v.y * t.y;
        im += v.x * t.y + v.y * t.x;
    }
    g_T2[g] = make_float2(re, im);
}

__global__ void k_i3() {                  // 12 -> 96 along x, real part -> g_h1
    int line = blockIdx.x;                // (b,c,s,z)
    int x = threadIdx.x;                  // 0..95
    __shared__ float2 cf[KX];
    if (x < KX) cf[x] = g_T2[line * KX + x];
    __syncthreads();
    const float2* tw = g_twIx + x * KX;
    float acc = 0.f;
#pragma unroll
    for (int k = 0; k < KX; k++)
        acc += cf[k].x * tw[k].x - cf[k].y * tw[k].y;
    g_h1[line * NX + x] = acc;
}

// ---------------- pointwise conv (w path) + add into g_h1 ----------------
__global__ void k_w(int sel, int L, const float* __restrict__ ww,
                    const float* __restrict__ wb) {
    __shared__ float sW[C * C];
    for (int i = threadIdx.x; i < C * C; i += blockDim.x)
        sW[i] = ww[L * C * C + i];
    __syncthreads();
    int p = blockIdx.x * blockDim.x + threadIdx.x;
    if (p >= NPT) return;
    int b = p / P, p0 = p % P;
    const float* h = hbuf(sel) + b * C * P + p0;
    float acc[C];
#pragma unroll
    for (int co = 0; co < C; co++) acc[co] = wb[L * C + co];
    for (int ci = 0; ci < C; ci++) {
        float v = h[ci * P];
#pragma unroll
        for (int co = 0; co < C; co++) acc[co] += sW[co * C + ci] * v;
    }
    float* o = g_h1 + b * C * P + p0;
#pragma unroll
    for (int co = 0; co < C; co++) o[co * P] += acc[co];
}

// ---------------- batchnorm ----------------
__global__ void k_zero() {
    if (threadIdx.x < C) { g_sum[threadIdx.x] = 0.0; g_sq[threadIdx.x] = 0.0; }
}

__global__ void k_stat() {
    int bid = blockIdx.x;
    int c = (bid / (P / 1024)) % C;
    const float* src = g_h1 + (size_t)bid * 1024;
    float s = 0.f, q = 0.f;
    for (int i = threadIdx.x; i < 1024; i += blockDim.x) {
        float v = src[i]; s += v; q += v * v;
    }
#pragma unroll
    for (int o = 16; o; o >>= 1) {
        s += __shfl_down_sync(0xffffffffu, s, o);
        q += __shfl_down_sync(0xffffffffu, q, o);
    }
    __shared__ float ws[8], wq[8];
    int wid = threadIdx.x >> 5, lane = threadIdx.x & 31;
    if (lane == 0) { ws[wid] = s; wq[wid] = q; }
    __syncthreads();
    if (threadIdx.x == 0) {
        float S = 0.f, Q = 0.f;
        int nw = blockDim.x >> 5;
        for (int i = 0; i < nw; i++) { S += ws[i]; Q += wq[i]; }
        atomicAdd(&g_sum[c], (double)S);
        atomicAdd(&g_sq[c],  (double)Q);
    }
}

__global__ void k_fin(int L, const float* __restrict__ bg, const float* __restrict__ bb) {
    int c = threadIdx.x;
    if (c < C) {
        double n = (double)NPT;
        double m = g_sum[c] / n;
        double var = g_sq[c] / n - m * m;
        float sc = bg[L * C + c] * (float)(1.0 / sqrt(var + 1e-5));
        g_scale[c] = sc;
        g_shift[c] = bb[L * C + c] - (float)m * sc;
    }
}

__global__ void k_bnapply(int outsel) {
    int idx = blockIdx.x * blockDim.x + threadIdx.x;
    int c = (idx / P) % C;
    float v = g_h1[idx] * g_scale[c] + g_shift[c];
    hbuf(outsel)[idx] = lrelu(v);
}

// ---------------- fused MLP + mask ----------------
constexpr int OW1 = 0,      OB1 = 4096;
constexpr int OW2 = 4224,   OB2 = 12416;
constexpr int OW3 = 12480,  OB3 = 14528;
constexpr int OW4 = 14560,  OB4 = 16608;
constexpr int OW5 = 16672,  OB5 = 24864;
constexpr int OW7 = 24992,  OB7 = 25120;
constexpr int SM_FLOATS = 25121;
constexpr int SMEM_MLP = SM_FLOATS * 4;

__global__ void __launch_bounds__(256, 1) k_mlp(
    const float* __restrict__ x,
    const float* __restrict__ w1, const float* __restrict__ b1,
    const float* __restrict__ w2, const float* __restrict__ b2,
    const float* __restrict__ w3, const float* __restrict__ b3,
    const float* __restrict__ w4, const float* __restrict__ b4,
    const float* __restrict__ w5, const float* __restrict__ b5,
    const float* __restrict__ w7, const float* __restrict__ b7,
    float* __restrict__ out) {
    extern __shared__ float sm[];
    int tid = threadIdx.x;
    for (int i = tid; i < 4096; i += 256) sm[OW1 + i] = w1[i];
    for (int i = tid; i < 128;  i += 256) sm[OB1 + i] = b1[i];
    for (int i = tid; i < 8192; i += 256) sm[OW2 + i] = w2[i];
    for (int i = tid; i < 64;   i += 256) sm[OB2 + i] = b2[i];
    for (int i = tid; i < 2048; i += 256) sm[OW3 + i] = w3[i];
    for (int i = tid; i < 32;   i += 256) sm[OB3 + i] = b3[i];
    for (int i = tid; i < 2048; i += 256) sm[OW4 + i] = w4[i];
    for (int i = tid; i < 64;   i += 256) sm[OB4 + i] = b4[i];
    for (int i = tid; i < 8192; i += 256) sm[OW5 + i] = w5[i];
    for (int i = tid; i < 128;  i += 256) sm[OB5 + i] = b5[i];
    for (int i = tid; i < 128;  i += 256) sm[OW7 + i] = w7[i];
    if (tid == 0) sm[OB7] = b7[0];
    __syncthreads();

    int p = blockIdx.x * blockDim.x + tid;
    int b = p / P, p0 = p % P;
    const float* h = g_hA + b * C * P + p0;   // final activations live in hA
    float in[32];
#pragma unroll
    for (int i = 0; i < 32; i++) in[i] = h[i * P];

    float a2[64];
#pragma unroll
    for (int k = 0; k < 64; k++) a2[k] = sm[OB2 + k];
#pragma unroll 1
    for (int j = 0; j < 128; j++) {
        float a = sm[OB1 + j];
#pragma unroll
        for (int i = 0; i < 32; i++) a += in[i] * sm[OW1 + i * 128 + j];
        a = lrelu(a);
#pragma unroll
        for (int k = 0; k < 64; k++) a2[k] += a * sm[OW2 + j * 64 + k];
    }
#pragma unroll
    for (int k = 0; k < 64; k++) a2[k] = lrelu(a2[k]);

    float a3[32];
#pragma unroll
    for (int k = 0; k < 32; k++) a3[k] = sm[OB3 + k];
#pragma unroll 1
    for (int j = 0; j < 64; j++) {
        float a = a2[j];
#pragma unroll
        for (int k = 0; k < 32; k++) a3[k] += a * sm[OW3 + j * 32 + k];
    }
#pragma unroll
    for (int k = 0; k < 32; k++) a3[k] = lrelu(a3[k]);

    float a4[64];
#pragma unroll
    for (int k = 0; k < 64; k++) a4[k] = sm[OB4 + k];
#pragma unroll 1
    for (int j = 0; j < 32; j++) {
        float a = a3[j];
#pragma unroll
        for (int k = 0; k < 64; k++) a4[k] += a * sm[OW4 + j * 64 + k];
    }
#pragma unroll
    for (int k = 0; k < 64; k++) a4[k] = lrelu(a4[k]);

    float tau = sm[OB7];
#pragma unroll 1
    for (int k = 0; k < 128; k++) {
        float a = sm[OB5 + k];
#pragma unroll
        for (int j = 0; j < 64; j++) a += a4[j] * sm[OW5 + j * 128 + k];
        a = lrelu(a);
        tau += a * sm[OW7 + k];
    }

    float T0 = x[2 * p + 1];
    int z = (p0 / NX) % NZ;
    float mask = (z < 2) ? 0.f : ((T0 < 0.01f) ? T0 : 1.f);
    out[p] = tau * mask;
}

// ---------------- loss ----------------
__global__ void k_loss(const float* __restrict__ y, float* __restrict__ out) {
    int p = blockIdx.x * blockDim.x + threadIdx.x;
    if (p >= NPT) return;
    int p0 = p % P;
    int xx = p0 % NX;
    int z = (p0 / NX) % NZ;
    const float* tau = out;
    float tm = (xx > 0)      ? tau[p - 1]  : 0.f;
    float tp = (xx < NX - 1) ? tau[p + 1]  : 0.f;
    float dx = (tp - tm) * INV2DX + g_t0dx[p];
    float zm = (z > 0)       ? tau[p - NX] : 0.f;
    float zp = (z < NZ - 1)  ? tau[p + NX] : 0.f;
    float dz = (zp - zm) * INV2DX + g_t0dz[p];
    out[NPT + p] = dx * dx + dz * dz - y[p];
}

// ---------------- launch ----------------
extern "C" void kernel_launch(void* const* d_in, const int* in_sizes, int n_in,
                              void* d_out, int out_size) {
    const float* x      = (const float*)d_in[0];
    const float* y      = (const float*)d_in[1];
    const float* fc0_w  = (const float*)d_in[2];
    const float* fc0_b  = (const float*)d_in[3];
    const float* spec_w = (const float*)d_in[4];
    const float* w_w    = (const float*)d_in[5];
    const float* w_b    = (const float*)d_in[6];
    const float* bn_g   = (const float*)d_in[7];
    const float* bn_b   = (const float*)d_in[8];
    const float* fc1_w  = (const float*)d_in[9];
    const float* fc1_b  = (const float*)d_in[10];
    const float* fc2_w  = (const float*)d_in[11];
    const float* fc2_b  = (const float*)d_in[12];
    const float* fc3_w  = (const float*)d_in[13];
    const float* fc3_b  = (const float*)d_in[14];
    const float* fc4_w  = (const float*)d_in[15];
    const float* fc4_b  = (const float*)d_in[16];
    const float* fc5_w  = (const float*)d_in[17];
    const float* fc5_b  = (const float*)d_in[18];
    const float* fc7_w  = (const float*)d_in[19];
    const float* fc7_b  = (const float*)d_in[20];
    float* out = (float*)d_out;

    cudaFuncSetAttribute(k_mlp, cudaFuncAttributeMaxDynamicSharedMemorySize, SMEM_MLP);

    k_init_tw<<<32, 256>>>();
    k_fc0t0<<<NPT / 256, 256>>>(x, fc0_w, fc0_b);

    for (int L = 0; L < 4; L++) {
        int sel = L & 1;          // input buffer: 0 -> hA, 1 -> hB
        k_f1<<<(B * C * NS * NZ * KX) / 256, 256>>>(sel);
        k_f2<<<(B * C * NS * KZ * KX) / 256, 256>>>();
        k_f3<<<(B * C * KS * KZ * KX) / 256, 256>>>();
        k_mul<<<(B * C * KS * KZ * KX) / 256, 256>>>(L, spec_w);
        k_i1<<<(B * C * NS * KZ * KX) / 256, 256>>>();
        k_i2<<<(B * C * NS * NZ * KX) / 256, 256>>>();
        k_i3<<<B * C * NS * NZ, 96>>>();
        k_w<<<(NPT + 255) / 256, 256>>>(sel, L, w_w, w_b);
        k_zero<<<1, 32>>>();
        k_stat<<<B * C * (P / 1024), 256>>>();
        k_fin<<<1, 32>>>(L, bn_g, bn_b);
        k_bnapply<<<(B * C * P) / 256, 256>>>(1 - sel);
    }

    k_mlp<<<NPT / 256, 256, SMEM_MLP>>>(x,
        fc1_w, fc1_b, fc2_w, fc2_b, fc3_w, fc3_b,
        fc4_w, fc4_b, fc5_w, fc5_b, fc7_w, fc7_b, out);
    k_loss<<<NPT / 256, 256>>>(y, out);
}

// round 5
// speedup vs baseline: 2.1113x; 2.1113x over previous
#include <cuda_runtime.h>
#include <math.h>
#include <stdint.h>

typedef unsigned long long ull;

constexpr int B  = 2;
constexpr int C  = 32;
constexpr int NS = 32;
constexpr int NZ = 96;
constexpr int NX = 96;
constexpr int P  = NS * NZ * NX;
constexpr int NPT = B * P;
constexpr int M1 = 8, M2 = 12, M3 = 12;
constexpr int KS = 16, KZ = 24, KX = 12;
constexpr float SLOPE = 0.1f;
constexpr float INV2DX = 50.0f;

// ---------------- scratch ----------------
__device__ float  g_hA[B * C * P];
__device__ float  g_hB[B * C * P];
__device__ float2 g_S2[B * C * NS * KZ * KX];
__device__ float2 g_S3[B * C * KS * KZ * KX];
__device__ float2 g_G [B * C * KS * KZ * KX];
__device__ float2 g_T1[B * C * NS * KZ * KX];
__device__ float  g_t0dx[NPT];
__device__ float  g_t0dz[NPT];
__device__ double g_sum[C];
__device__ double g_sq[C];
__device__ float  g_scaleL[4 * C];
__device__ float  g_shiftL[4 * C];

// packed twiddles
__device__ ulonglong2 g_twFxP[KX * 48];   // ((c0,c1),(-s0,-s1))/NX  (x-pairs)
__device__ ulonglong2 g_twFzP[KZ * NZ];   // ((c,s'),(-s',c))/NZ, s'=-sin
__device__ ulonglong2 g_twIzP[NZ * KZ];   // ((c,s),(-s,c)) inverse
__device__ ulonglong2 g_twIxP[48 * KX];   // ((c0,c1),(-s0,-s1)) inverse
__device__ float2 g_twFs[KS * NS];
__device__ float2 g_twIs[NS * KS];

__device__ __forceinline__ float lrelu(float v) { return v > 0.f ? v : SLOPE * v; }
__device__ __forceinline__ float* hbuf(int s) { return s ? g_hB : g_hA; }
__device__ __forceinline__ ull pk(float a, float b) {
    ull r; asm("mov.b64 %0,{%1,%2};" : "=l"(r) : "f"(a), "f"(b)); return r;
}
__device__ __forceinline__ void upk(ull v, float& a, float& b) {
    asm("mov.b64 {%0,%1},%2;" : "=f"(a), "=f"(b) : "l"(v));
}
__device__ __forceinline__ ull fma2(ull a, ull b, ull c) {
    ull d; asm("fma.rn.f32x2 %0,%1,%2,%3;" : "=l"(d) : "l"(a), "l"(b), "l"(c)); return d;
}

// ---------------- twiddle init ----------------
__global__ void k_init_tw() {
    int t = blockIdx.x * blockDim.x + threadIdx.x;
    if (t < 576) {                    // FxP: k<12, xh<48
        int k = t / 48, xh = t % 48;
        double s0, c0, s1, c1;
        sincospi(2.0 * double((k * (2 * xh)) % NX) / NX, &s0, &c0);
        sincospi(2.0 * double((k * (2 * xh + 1)) % NX) / NX, &s1, &c1);
        g_twFxP[t].x = pk((float)(c0 / NX), (float)(c1 / NX));
        g_twFxP[t].y = pk((float)(-s0 / NX), (float)(-s1 / NX));
    }
    if (t < 2304) {                   // FzP: kzi<24, z<96
        int kzi = t / 96, z = t % 96;
        int kz = (kzi < M2) ? kzi : kzi + (NZ - KZ);
        double s, c; sincospi(2.0 * double((kz * z) % NZ) / NZ, &s, &c);
        float tx = (float)(c / NZ), ty = (float)(-s / NZ);
        g_twFzP[t].x = pk(tx, ty); g_twFzP[t].y = pk(-ty, tx);
    }
    if (t < 2304) {                   // IzP: z<96, k<24
        int z = t / 24, k = t % 24;
        int kz = (k < M2) ? k : k + (NZ - KZ);
        double s, c; sincospi(2.0 * double((kz * z) % NZ) / NZ, &s, &c);
        float tx = (float)c, ty = (float)s;
        g_twIzP[t].x = pk(tx, ty); g_twIzP[t].y = pk(-ty, tx);
    }
    if (t < 576) {                    // IxP: xh<48, k<12
        int xh = t / 12, k = t % 12;
        double s0, c0, s1, c1;
        sincospi(2.0 * double((k * (2 * xh)) % NX) / NX, &s0, &c0);
        sincospi(2.0 * double((k * (2 * xh + 1)) % NX) / NX, &s1, &c1);
        g_twIxP[t].x = pk((float)c0, (float)c1);
        g_twIxP[t].y = pk((float)(-s0), (float)(-s1));
    }
    if (t < 512) {                    // Fs: ksi<16, s<32
        int ksi = t / 32, s0i = t % 32;
        int ks = (ksi < M1) ? ksi : ksi + (NS - KS);
        double s, c; sincospi(2.0 * double((ks * s0i) % NS) / NS, &s, &c);
        g_twFs[t] = make_float2((float)(c / NS), (float)(-s / NS));
    }
    if (t < 512) {                    // Is: s<32, k<16
        int s0i = t / 16, k = t % 16;
        int ks = (k < M1) ? k : k + (NS - KS);
        double s, c; sincospi(2.0 * double((ks * s0i) % NS) / NS, &s, &c);
        g_twIs[t] = make_float2((float)c, (float)s);
    }
}

// ---------------- fc0 + T0 derivatives ----------------
__global__ void k_fc0t0(const float* __restrict__ x, const float* __restrict__ w,
                        const float* __restrict__ bb) {
    int p = blockIdx.x * blockDim.x + threadIdx.x;
    if (p >= NPT) return;
    int b = p / P, p0 = p % P;
    int xx = p0 % NX;
    int z  = (p0 / NX) % NZ;
    float a0 = x[2 * p], a1 = x[2 * p + 1];
#pragma unroll
    for (int c = 0; c < C; c++)
        g_hA[(b * C + c) * P + p0] = a0 * w[c] + a1 * w[C + c] + bb[c];
    float xm = (xx > 0)      ? x[2 * (p - 1) + 1]  : 0.f;
    float xp = (xx < NX - 1) ? x[2 * (p + 1) + 1]  : 0.f;
    g_t0dx[p] = (xp - xm) * INV2DX;
    float zm = (z > 0)       ? x[2 * (p - NX) + 1] : 0.f;
    float zp = (z < NZ - 1)  ? x[2 * (p + NX) + 1] : 0.f;
    g_t0dz[p] = (zp - zm) * INV2DX;
}

// ---------------- fused forward DFT (x then z) per (b,c,s) slab ----------------
// dyn smem: slab f[9216] @0 | s1re ull[1152] @36864 | s1im @46080
constexpr int SMEM_FWD = 55296;
__global__ void __launch_bounds__(256) k_fwd(int selIn, int Lprev) {
    extern __shared__ char smraw[];
    float* slab = (float*)smraw;
    ull*   s1re = (ull*)(smraw + 36864);
    ull*   s1im = (ull*)(smraw + 46080);
    int bid = blockIdx.x, tid = threadIdx.x;
    int c = (bid / NS) % C;
    float sc = 1.f, sh = 0.f;
    if (Lprev >= 0) { sc = g_scaleL[Lprev * C + c]; sh = g_shiftL[Lprev * C + c]; }
    const float* base = hbuf(selIn) + (size_t)bid * 9216;
    for (int i = tid; i < 9216; i += 256) {
        float v = base[i];
        if (Lprev >= 0) v = lrelu(fmaf(v, sc, sh));
        slab[i] = v;
    }
    __syncthreads();
    // stage 1: x-DFT real->complex, packed x-pairs
    for (int it = tid; it < 1152; it += 256) {
        int k = it % 12, z = it / 12;
        ull ar = 0, ai = 0;
        const float* row = slab + z * 96;
        const ulonglong2* tw = g_twFxP + k * 48;
#pragma unroll 12
        for (int xh = 0; xh < 48; xh++) {
            ull v = *(const ull*)(row + 2 * xh);
            ulonglong2 t = tw[xh];
            ar = fma2(v, t.x, ar);
            ai = fma2(v, t.y, ai);
        }
        float r0, r1, i0, i1; upk(ar, r0, r1); upk(ai, i0, i1);
        float re = r0 + r1, im = i0 + i1;
        s1re[it] = pk(re, re);
        s1im[it] = pk(im, im);
    }
    __syncthreads();
    // stage 2: z-DFT complex, acc packed (re,im)
    for (int it = tid; it < 288; it += 256) {
        int kx = it % 12, kz = it / 12;
        ull acc = 0;
        const ulonglong2* tw = g_twFzP + kz * 96;
#pragma unroll 8
        for (int z = 0; z < 96; z++) {
            ulonglong2 t = tw[z];
            acc = fma2(s1re[z * 12 + kx], t.x, acc);
            acc = fma2(s1im[z * 12 + kx], t.y, acc);
        }
        float2 o; upk(acc, o.x, o.y);
        g_S2[(size_t)bid * 288 + it] = o;
    }
}

// ---------------- forward s-DFT ----------------
__global__ void k_f3() {
    int g = blockIdx.x * blockDim.x + threadIdx.x;
    int kx = g % KX, kzi = (g / KX) % KZ, ksi = (g / 288) % KS, bc = g / 4608;
    const float2* src = g_S2 + bc * NS * 288 + kzi * KX + kx;
    const float2* tw  = g_twFs + ksi * NS;
    float re = 0.f, im = 0.f;
#pragma unroll 8
    for (int s = 0; s < NS; s++) {
        float2 v = src[s * 288]; float2 t = tw[s];
        re += v.x * t.x - v.y * t.y;
        im += v.x * t.y + v.y * t.x;
    }
    g_S3[(bc * KS + ksi) * 288 + kzi * KX + kx] = make_float2(re, im);
}

// ---------------- spectral multiply ----------------
__global__ void k_mul(int L, const float* __restrict__ spec) {
    int g = blockIdx.x * blockDim.x + threadIdx.x;
    int kx = g % KX, kzi = (g / KX) % KZ, ksi = (g / 288) % KS;
    int co = (g / 4608) % C, b = g / (4608 * C);
    int corner = (ksi >= M1 ? 1 : 0) + (kzi >= M2 ? 2 : 0);
    int k1 = (ksi >= M1) ? ksi - M1 : ksi;
    int k2 = (kzi >= M2) ? kzi - M2 : kzi;
    int wbase = ((((L * 4 + corner) * C) * C + co) * M1 + k1) * M2 + k2;
    wbase = wbase * M3 + kx;
    const int wstride = C * M1 * M2 * M3;
    const float2* xin = g_S3 + (b * C) * 4608 + ksi * 288 + kzi * KX + kx;
    float re = 0.f, im = 0.f;
#pragma unroll 8
    for (int ci = 0; ci < C; ci++) {
        float2 a = xin[ci * 4608];
        float wr = spec[2 * (wbase + ci * wstride)];
        float wi = spec[2 * (wbase + ci * wstride) + 1];
        re += a.x * wr - a.y * wi;
        im += a.x * wi + a.y * wr;
    }
    g_G[g] = make_float2(re, im);
}

// ---------------- inverse s-DFT ----------------
__global__ void k_i1() {
    int g = blockIdx.x * blockDim.x + threadIdx.x;
    int kx = g % KX, kzi = (g / KX) % KZ, s = (g / 288) % NS, bc = g / (288 * NS);
    const float2* src = g_G + bc * 4608 + kzi * KX + kx;
    const float2* tw  = g_twIs + s * KS;
    float re = 0.f, im = 0.f;
#pragma unroll
    for (int k = 0; k < KS; k++) {
        float2 v = src[k * 288]; float2 t = tw[k];
        re += v.x * t.x - v.y * t.y;
        im += v.x * t.y + v.y * t.x;
    }
    g_T1[g] = make_float2(re, im);
}

// ---------------- fused inverse DFT (z then x) per (b,c,s) slab ----------------
__global__ void __launch_bounds__(256) k_inv(int selOut) {
    __shared__ ull T1re[288], T1im[288];
    __shared__ ull T2re[1152], T2im[1152];
    int bid = blockIdx.x, tid = threadIdx.x;
    for (int i = tid; i < 288; i += 256) {
        float2 v = g_T1[(size_t)bid * 288 + i];
        T1re[i] = pk(v.x, v.x); T1im[i] = pk(v.y, v.y);
    }
    __syncthreads();
    // stage i2: 24 -> 96 along z
    for (int it = tid; it < 1152; it += 256) {
        int kx = it % 12, z = it / 12;
        ull acc = 0;
        const ulonglong2* tw = g_twIzP + z * 24;
#pragma unroll
        for (int k = 0; k < 24; k++) {
            ulonglong2 t = tw[k];
            acc = fma2(T1re[k * 12 + kx], t.x, acc);
            acc = fma2(T1im[k * 12 + kx], t.y, acc);
        }
        float re, im; upk(acc, re, im);
        T2re[it] = pk(re, re); T2im[it] = pk(im, im);
    }
    __syncthreads();
    // stage i3: 12 -> 96 along x, real output, packed x-pairs
    float* dst = hbuf(selOut) + (size_t)bid * 9216;
    for (int it = tid; it < 4608; it += 256) {
        int xh = it % 48, z = it / 48;
        ull acc = 0;
        const ulonglong2* tw = g_twIxP + xh * 12;
#pragma unroll
        for (int k = 0; k < 12; k++) {
            ulonglong2 t = tw[k];
            acc = fma2(T2re[z * 12 + k], t.x, acc);
            acc = fma2(T2im[z * 12 + k], t.y, acc);
        }
        float2 o; upk(acc, o.x, o.y);
        *(float2*)(dst + z * 96 + 2 * xh) = o;
    }
}

// ---------------- pointwise conv: OUT += W*act(BN(IN)) + b ----------------
__global__ void __launch_bounds__(256) k_w2(int selIn, int selOut, int Lprev, int L,
                                            const float* __restrict__ ww,
                                            const float* __restrict__ wb) {
    __shared__ ull sWP[C * 16];             // [ci][cop] pairs over co
    __shared__ float sB[32], sSc[32], sSh[32];
    int tid = threadIdx.x;
    for (int i = tid; i < 512; i += 256) {
        int cop = i & 15, ci = i >> 4;
        sWP[i] = pk(ww[L * 1024 + (2 * cop) * C + ci],
                    ww[L * 1024 + (2 * cop + 1) * C + ci]);
    }
    if (tid < 32) {
        sB[tid] = wb[L * C + tid];
        if (Lprev >= 0) { sSc[tid] = g_scaleL[Lprev * C + tid]; sSh[tid] = g_shiftL[Lprev * C + tid]; }
        else            { sSc[tid] = 1.f; sSh[tid] = 0.f; }
    }
    __syncthreads();
    int p = blockIdx.x * 256 + tid;
    int b = p / P, p0 = p % P;
    const float* h = hbuf(selIn) + b * C * P + p0;
    ull acc[16];
#pragma unroll
    for (int cop = 0; cop < 16; cop++) acc[cop] = pk(sB[2 * cop], sB[2 * cop + 1]);
    int useBn = (Lprev >= 0);
#pragma unroll
    for (int ci = 0; ci < 32; ci++) {
        float v = h[ci * P];
        if (useBn) v = lrelu(fmaf(v, sSc[ci], sSh[ci]));
        ull vp = pk(v, v);
        const ulonglong2* wr = (const ulonglong2*)&sWP[ci * 16];
#pragma unroll
        for (int q = 0; q < 8; q++) {
            ulonglong2 w = wr[q];
            acc[2 * q]     = fma2(vp, w.x, acc[2 * q]);
            acc[2 * q + 1] = fma2(vp, w.y, acc[2 * q + 1]);
        }
    }
    float* o = hbuf(selOut) + b * C * P + p0;
#pragma unroll
    for (int cop = 0; cop < 16; cop++) {
        float f0, f1; upk(acc[cop], f0, f1);
        o[(2 * cop) * P]     += f0;
        o[(2 * cop + 1) * P] += f1;
    }
}

// ---------------- batchnorm stats ----------------
__global__ void k_zero() {
    if (threadIdx.x < C) { g_sum[threadIdx.x] = 0.0; g_sq[threadIdx.x] = 0.0; }
}

__global__ void k_stat(int selOut) {
    int bid = blockIdx.x;
    int c = (bid / (P / 1024)) % C;
    const float4* src = (const float4*)(hbuf(selOut) + (size_t)bid * 1024);
    float4 v = src[threadIdx.x];
    float s = v.x + v.y + v.z + v.w;
    float q = v.x * v.x + v.y * v.y + v.z * v.z + v.w * v.w;
#pragma unroll
    for (int o = 16; o; o >>= 1) {
        s += __shfl_down_sync(0xffffffffu, s, o);
        q += __shfl_down_sync(0xffffffffu, q, o);
    }
    __shared__ float ws[8], wq[8];
    int wid = threadIdx.x >> 5, lane = threadIdx.x & 31;
    if (lane == 0) { ws[wid] = s; wq[wid] = q; }
    __syncthreads();
    if (threadIdx.x == 0) {
        float S = 0.f, Q = 0.f;
        for (int i = 0; i < 8; i++) { S += ws[i]; Q += wq[i]; }
        atomicAdd(&g_sum[c], (double)S);
        atomicAdd(&g_sq[c],  (double)Q);
    }
}

__global__ void k_fin(int L, const float* __restrict__ bg, const float* __restrict__ bb) {
    int c = threadIdx.x;
    if (c < C) {
        double n = (double)NPT;
        double m = g_sum[c] / n;
        double var = g_sq[c] / n - m * m;
        float sc = bg[L * C + c] * (float)(1.0 / sqrt(var + 1e-5));
        g_scaleL[L * C + c] = sc;
        g_shiftL[L * C + c] = bb[L * C + c] - (float)m * sc;
    }
}

// ---------------- fused MLP + mask (f32x2, transposed weights) ----------------
constexpr int OW1T = 0,      OB1 = 4096;
constexpr int OW2  = 4224,   OB2 = 12416;
constexpr int OW3T = 12480,  OB3 = 14528;
constexpr int OW4T = 14560,  OB4 = 16608;
constexpr int OW5T = 16672,  OB5 = 24864;
constexpr int OW7  = 24992,  OB7 = 25120;
constexpr int OSC  = 25121,  OSH = 25153;
constexpr int SMEM_MLP = 25185 * 4;

__global__ void __launch_bounds__(256, 1) k_mlp(
    const float* __restrict__ x,
    const float* __restrict__ w1, const float* __restrict__ b1,
    const float* __restrict__ w2, const float* __restrict__ b2,
    const float* __restrict__ w3, const float* __restrict__ b3,
    const float* __restrict__ w4, const float* __restrict__ b4,
    const float* __restrict__ w5, const float* __restrict__ b5,
    const float* __restrict__ w7, const float* __restrict__ b7,
    float* __restrict__ out) {
    extern __shared__ float sm[];
    int tid = threadIdx.x;
    for (int i = tid; i < 4096; i += 256) {          // w1 transpose [j][i]
        int r = i >> 7, j = i & 127;
        sm[OW1T + j * 32 + r] = w1[i];
    }
    for (int i = tid; i < 128;  i += 256) sm[OB1 + i] = b1[i];
    for (int i = tid; i < 8192; i += 256) sm[OW2 + i] = w2[i];   // row-major
    for (int i = tid; i < 64;   i += 256) sm[OB2 + i] = b2[i];
    for (int i = tid; i < 2048; i += 256) {          // w3 transpose [k][j]
        int j = i >> 5, k = i & 31;
        sm[OW3T + k * 64 + j] = w3[i];
    }
    for (int i = tid; i < 32;   i += 256) sm[OB3 + i] = b3[i];
    for (int i = tid; i < 2048; i += 256) {          // w4 transpose [k][j]
        int j = i >> 6, k = i & 63;
        sm[OW4T + k * 32 + j] = w4[i];
    }
    for (int i = tid; i < 64;   i += 256) sm[OB4 + i] = b4[i];
    for (int i = tid; i < 8192; i += 256) {          // w5 transpose [k][j]
        int j = i >> 7, k = i & 127;
        sm[OW5T + k * 64 + j] = w5[i];
    }
    for (int i = tid; i < 128;  i += 256) sm[OB5 + i] = b5[i];
    for (int i = tid; i < 128;  i += 256) sm[OW7 + i] = w7[i];
    if (tid == 0) sm[OB7] = b7[0];
    if (tid < 32) { sm[OSC + tid] = g_scaleL[3 * C + tid]; sm[OSH + tid] = g_shiftL[3 * C + tid]; }
    __syncthreads();

    int p = blockIdx.x * 256 + tid;
    int b = p / P, p0 = p % P;
    const float* h = g_hA + b * C * P + p0;
    ull inl[16];
#pragma unroll
    for (int i = 0; i < 16; i++) {
        float v0 = lrelu(fmaf(h[(2 * i) * P],     sm[OSC + 2 * i],     sm[OSH + 2 * i]));
        float v1 = lrelu(fmaf(h[(2 * i + 1) * P], sm[OSC + 2 * i + 1], sm[OSH + 2 * i + 1]));
        inl[i] = pk(v0, v1);
    }

    // L1 (reduce over i) interleaved with L2 accumulation (broadcast over k)
    ull a2[32];
#pragma unroll
    for (int k = 0; k < 32; k++) a2[k] = *(const ull*)&sm[OB2 + 2 * k];
#pragma unroll 1
    for (int j = 0; j < 128; j += 2) {
        ull acc0 = 0, acc1 = 0;
        const ulonglong2* wr0 = (const ulonglong2*)&sm[OW1T + j * 32];
        const ulonglong2* wr1 = (const ulonglong2*)&sm[OW1T + (j + 1) * 32];
#pragma unroll
        for (int m = 0; m < 8; m++) {
            ulonglong2 t0 = wr0[m], t1 = wr1[m];
            acc0 = fma2(inl[2 * m], t0.x, acc0);
            acc0 = fma2(inl[2 * m + 1], t0.y, acc0);
            acc1 = fma2(inl[2 * m], t1.x, acc1);
            acc1 = fma2(inl[2 * m + 1], t1.y, acc1);
        }
        float u0, u1, v0, v1; upk(acc0, u0, u1); upk(acc1, v0, v1);
        float a0 = lrelu(u0 + u1 + sm[OB1 + j]);
        float a1v = lrelu(v0 + v1 + sm[OB1 + j + 1]);
        ull q0 = pk(a0, a0), q1 = pk(a1v, a1v);
        const ulonglong2* r0 = (const ulonglong2*)&sm[OW2 + j * 64];
        const ulonglong2* r1 = (const ulonglong2*)&sm[OW2 + (j + 1) * 64];
#pragma unroll
        for (int m = 0; m < 16; m++) {
            ulonglong2 t0 = r0[m], t1 = r1[m];
            a2[2 * m]     = fma2(q0, t0.x, a2[2 * m]);
            a2[2 * m + 1] = fma2(q0, t0.y, a2[2 * m + 1]);
            a2[2 * m]     = fma2(q1, t1.x, a2[2 * m]);
            a2[2 * m + 1] = fma2(q1, t1.y, a2[2 * m + 1]);
        }
    }
    ull a2l[32];
#pragma unroll
    for (int k = 0; k < 32; k++) {
        float u, v; upk(a2[k], u, v);
        a2l[k] = pk(lrelu(u), lrelu(v));
    }

    // L3: 64 -> 32 (reduce over j pairs, transposed w3)
    ull a3l[16];
#pragma unroll 1
    for (int k = 0; k < 32; k += 2) {
        ull acc0 = 0, acc1 = 0;
        const ulonglong2* r0 = (const ulonglong2*)&sm[OW3T + k * 64];
        const ulonglong2* r1 = (const ulonglong2*)&sm[OW3T + (k + 1) * 64];
#pragma unroll
        for (int m = 0; m < 16; m++) {
            ulonglong2 t0 = r0[m], t1 = r1[m];
            acc0 = fma2(a2l[2 * m], t0.x, acc0);
            acc0 = fma2(a2l[2 * m + 1], t0.y, acc0);
            acc1 = fma2(a2l[2 * m], t1.x, acc1);
            acc1 = fma2(a2l[2 * m + 1], t1.y, acc1);
        }
        float u0, u1, v0, v1; upk(acc0, u0, u1); upk(acc1, v0, v1);
        a3l[k >> 1] = pk(lrelu(u0 + u1 + sm[OB3 + k]),
                         lrelu(v0 + v1 + sm[OB3 + k + 1]));
    }

    // L4: 32 -> 64 (reduce, transposed w4)
    ull a4l[32];
#pragma unroll 1
    for (int k = 0; k < 64; k += 2) {
        ull acc0 = 0, acc1 = 0;
        const ulonglong2* r0 = (const ulonglong2*)&sm[OW4T + k * 32];
        const ulonglong2* r1 = (const ulonglong2*)&sm[OW4T + (k + 1) * 32];
#pragma unroll
        for (int m = 0; m < 8; m++) {
            ulonglong2 t0 = r0[m], t1 = r1[m];
            acc0 = fma2(a3l[2 * m], t0.x, acc0);
            acc0 = fma2(a3l[2 * m + 1], t0.y, acc0);
            acc1 = fma2(a3l[2 * m], t1.x, acc1);
            acc1 = fma2(a3l[2 * m + 1], t1.y, acc1);
        }
        float u0, u1, v0, v1; upk(acc0, u0, u1); upk(acc1, v0, v1);
        a4l[k >> 1] = pk(lrelu(u0 + u1 + sm[OB4 + k]),
                         lrelu(v0 + v1 + sm[OB4 + k + 1]));
    }

    // L5: 64 -> 128 (reduce, transposed w5) streamed into fc7
    float tau = sm[OB7];
#pragma unroll 1
    for (int k = 0; k < 128; k += 2) {
        ull acc0 = 0, acc1 = 0;
        const ulonglong2* r0 = (const ulonglong2*)&sm[OW5T + k * 64];
        const ulonglong2* r1 = (const ulonglong2*)&sm[OW5T + (k + 1) * 64];
#pragma unroll
        for (int m = 0; m < 16; m++) {
            ulonglong2 t0 = r0[m], t1 = r1[m];
            acc0 = fma2(a4l[2 * m], t0.x, acc0);
            acc0 = fma2(a4l[2 * m + 1], t0.y, acc0);
            acc1 = fma2(a4l[2 * m], t1.x, acc1);
            acc1 = fma2(a4l[2 * m + 1], t1.y, acc1);
        }
        float u0, u1, v0, v1; upk(acc0, u0, u1); upk(acc1, v0, v1);
        float a5a = lrelu(u0 + u1 + sm[OB5 + k]);
        float a5b = lrelu(v0 + v1 + sm[OB5 + k + 1]);
        tau += a5a * sm[OW7 + k] + a5b * sm[OW7 + k + 1];
    }

    float T0 = x[2 * p + 1];
    int z = (p0 / NX) % NZ;
    float mask = (z < 2) ? 0.f : ((T0 < 0.01f) ? T0 : 1.f);
    out[p] = tau * mask;
}

// ---------------- loss ----------------
__global__ void k_loss(const float* __restrict__ y, float* __restrict__ out) {
    int p = blockIdx.x * blockDim.x + threadIdx.x;
    if (p >= NPT) return;
    int p0 = p % P;
    int xx = p0 % NX;
    int z = (p0 / NX) % NZ;
    const float* tau = out;
    float tm = (xx > 0)      ? tau[p - 1]  : 0.f;
    float tp = (xx < NX - 1) ? tau[p + 1]  : 0.f;
    float dx = (tp - tm) * INV2DX + g_t0dx[p];
    float zm = (z > 0)       ? tau[p - NX] : 0.f;
    float zp = (z < NZ - 1)  ? tau[p + NX] : 0.f;
    float dz = (zp - zm) * INV2DX + g_t0dz[p];
    out[NPT + p] = dx * dx + dz * dz - y[p];
}

// ---------------- launch ----------------
extern "C" void kernel_launch(void* const* d_in, const int* in_sizes, int n_in,
                              void* d_out, int out_size) {
    const float* x      = (const float*)d_in[0];
    const float* y      = (const float*)d_in[1];
    const float* fc0_w  = (const float*)d_in[2];
    const float* fc0_b  = (const float*)d_in[3];
    const float* spec_w = (const float*)d_in[4];
    const float* w_w    = (const float*)d_in[5];
    const float* w_b    = (const float*)d_in[6];
    const float* bn_g   = (const float*)d_in[7];
    const float* bn_b   = (const float*)d_in[8];
    const float* fc1_w  = (const float*)d_in[9];
    const float* fc1_b  = (const float*)d_in[10];
    const float* fc2_w  = (const float*)d_in[11];
    const float* fc2_b  = (const float*)d_in[12];
    const float* fc3_w  = (const float*)d_in[13];
    const float* fc3_b  = (const float*)d_in[14];
    const float* fc4_w  = (const float*)d_in[15];
    const float* fc4_b  = (const float*)d_in[16];
    const float* fc5_w  = (const float*)d_in[17];
    const float* fc5_b  = (const float*)d_in[18];
    const float* fc7_w  = (const float*)d_in[19];
    const float* fc7_b  = (const float*)d_in[20];
    float* out = (float*)d_out;

    cudaFuncSetAttribute(k_fwd, cudaFuncAttributeMaxDynamicSharedMemorySize, SMEM_FWD);
    cudaFuncSetAttribute(k_mlp, cudaFuncAttributeMaxDynamicSharedMemorySize, SMEM_MLP);

    k_init_tw<<<9, 256>>>();
    k_fc0t0<<<NPT / 256, 256>>>(x, fc0_w, fc0_b);

    for (int L = 0; L < 4; L++) {
        int in = L & 1, outb = 1 - in, Lp = L - 1;
        k_fwd<<<B * C * NS, 256, SMEM_FWD>>>(in, Lp);
        k_f3<<<(B * C * KS * KZ * KX) / 256, 256>>>();
        k_mul<<<(B * C * KS * KZ * KX) / 256, 256>>>(L, spec_w);
        k_i1<<<(B * C * NS * KZ * KX) / 256, 256>>>();
        k_inv<<<B * C * NS, 256>>>(outb);
        k_w2<<<NPT / 256, 256>>>(in, outb, Lp, L, w_w, w_b);
        k_zero<<<1, 32>>>();
        k_stat<<<B * C * (P / 1024), 256>>>(outb);
        k_fin<<<1, 32>>>(L, bn_g, bn_b);
    }

    k_mlp<<<NPT / 256, 256, SMEM_MLP>>>(x,
        fc1_w, fc1_b, fc2_w, fc2_b, fc3_w, fc3_b,
        fc4_w, fc4_b, fc5_w, fc5_b, fc7_w, fc7_b, out);
    k_loss<<<NPT / 256, 256>>>(y, out);
}